// round 12
// baseline (speedup 1.0000x reference)
#include <cuda_runtime.h>
#include <cstdint>

#define NB 32
#define CD 64
#define TPB 256
#define ROWS 128

#define ASTR 68                     // f32 stride of z tile (conflict-free frag loads)
#define BSTR4 34                    // uint4 stride of packed B table
#define SSTR 36                     // f32 stride of sims tile

// dynamic smem offsets (bytes)
#define SM_Z     0                                   // 128 x 68 f32 = 34816 (aliased as sims later)
#define SM_B     34816                               // 32 x 34 uint4 = 17408
#define SM_RES   (SM_B + 17408)                      // 52224: 128 x float4
#define SM_HIST  (SM_RES + 2048)                     // 54272: 32 ints
#define SM_TOTAL (SM_HIST + 128)                     // 54400

__device__ __forceinline__ uint32_t f2tf(float x) {
    uint32_t r;
    asm("cvt.rna.tf32.f32 %0, %1;" : "=r"(r) : "f"(x));
    return r;
}
__device__ __forceinline__ void mma_tf32(float* c,
                                         uint32_t a0, uint32_t a1, uint32_t a2, uint32_t a3,
                                         uint32_t b0, uint32_t b1) {
    asm volatile(
        "mma.sync.aligned.m16n8k8.row.col.f32.tf32.tf32.f32 "
        "{%0,%1,%2,%3}, {%4,%5,%6,%7}, {%8,%9}, {%0,%1,%2,%3};"
        : "+f"(c[0]), "+f"(c[1]), "+f"(c[2]), "+f"(c[3])
        : "r"(a0), "r"(a1), "r"(a2), "r"(a3), "r"(b0), "r"(b1));
}

__global__ void gc_init_util(const float* __restrict__ u_in,
                             float* __restrict__ u_out) {
    int i = threadIdx.x;
    if (i < NB) u_out[i] = u_in[i];
}

__global__ __launch_bounds__(TPB, 3)
void gc_main(const float* __restrict__ z,
             const float* __restrict__ protos,
             float* __restrict__ act,
             float* __restrict__ assign,
             float* __restrict__ util,
             int B) {
    extern __shared__ char smem[];
    float*  s_z    = (float*)(smem + SM_Z);
    uint4*  s_bp   = (uint4*)(smem + SM_B);
    float*  s_sims = (float*)(smem + SM_Z);      // alias, used after sync
    float4* s_res  = (float4*)(smem + SM_RES);
    int*    s_hist = (int*)(smem + SM_HIST);

    const int tid  = threadIdx.x;
    const int base = blockIdx.x * ROWS;
    const int w    = tid >> 5;
    const int lane = tid & 31;
    const int g    = lane >> 2;      // groupID (row / n selector)
    const int c    = lane & 3;       // thread-in-group (k selector)

    // ---- stage packed B: entry [kc][n] = (bh[kr], bh[kr+4], bm[kr], bm[kr+4]), kr=8*(kc>>2)+(kc&3)
    #pragma unroll
    for (int it = 0; it < (32 * 32) / TPB; it++) {   // 4 iters
        int e  = it * TPB + tid;
        int kc = e >> 5;
        int n  = e & 31;
        int kr = ((kc >> 2) << 3) + (kc & 3);
        float p0 = protos[n * CD + kr];
        float p1 = protos[n * CD + kr + 4];
        uint32_t h0 = f2tf(p0);
        uint32_t h1 = f2tf(p1);
        uint32_t m0 = f2tf(p0 - __uint_as_float(h0));
        uint32_t m1 = f2tf(p1 - __uint_as_float(h1));
        s_bp[kc * BSTR4 + n] = make_uint4(h0, h1, m0, m1);
    }
    if (tid < NB) s_hist[tid] = 0;

    // ---- stage z fp32 tile: coalesced LDG.128, padded STS (zero-fill OOB)
    #pragma unroll
    for (int it = 0; it < (ROWS * 16) / TPB; it++) {  // 8 iters
        int idx = it * TPB + tid;
        int row = idx >> 4;
        int d4  = idx & 15;
        int grow = base + row;
        float4 v = make_float4(0.f, 0.f, 0.f, 0.f);
        if (grow < B) v = *(const float4*)(z + (size_t)grow * CD + d4 * 4);
        *(float4*)&s_z[row * ASTR + d4 * 4] = v;
    }
    __syncthreads();

    // ---- mainloop: warp owns rows [w*16, w*16+16); one m16 tile x 4 n-tiles
    float acc[4][4];
    #pragma unroll
    for (int nt = 0; nt < 4; nt++)
        #pragma unroll
        for (int j = 0; j < 4; j++) acc[nt][j] = 0.0f;

    const int rb = w * 16;
    const int r  = rb + g;

    #pragma unroll
    for (int k = 0; k < 8; k++) {
        const int kr = 8 * k + c;
        // packed B fragments: one LDS.128 per n-tile
        uint4 bq[4];
        #pragma unroll
        for (int nt = 0; nt < 4; nt++)
            bq[nt] = s_bp[(k * 4 + c) * BSTR4 + nt * 8 + g];
        // A fragment (fp32 -> tf32 h/m split)
        const float x0 = s_z[r * ASTR + kr];
        const float x1 = s_z[(r + 8) * ASTR + kr];
        const float x2 = s_z[r * ASTR + kr + 4];
        const float x3 = s_z[(r + 8) * ASTR + kr + 4];
        const uint32_t ah0 = f2tf(x0), ah1 = f2tf(x1);
        const uint32_t ah2 = f2tf(x2), ah3 = f2tf(x3);
        const uint32_t am0 = f2tf(x0 - __uint_as_float(ah0));
        const uint32_t am1 = f2tf(x1 - __uint_as_float(ah1));
        const uint32_t am2 = f2tf(x2 - __uint_as_float(ah2));
        const uint32_t am3 = f2tf(x3 - __uint_as_float(ah3));
        // product-major order: same-acc MMA spacing = 4
        #pragma unroll
        for (int nt = 0; nt < 4; nt++)
            mma_tf32(acc[nt], ah0, ah1, ah2, ah3, bq[nt].x, bq[nt].y);   // hh
        #pragma unroll
        for (int nt = 0; nt < 4; nt++)
            mma_tf32(acc[nt], ah0, ah1, ah2, ah3, bq[nt].z, bq[nt].w);   // hm
        #pragma unroll
        for (int nt = 0; nt < 4; nt++)
            mma_tf32(acc[nt], am0, am1, am2, am3, bq[nt].x, bq[nt].y);   // mh
    }
    __syncthreads();   // all z reads done; alias region as sims

    // ---- scatter C fragments to sims tile [row][32] (stride 36)
    #pragma unroll
    for (int nt = 0; nt < 4; nt++) {
        const int col = nt * 8 + 2 * c;
        *(float2*)&s_sims[r * SSTR + col]       = make_float2(acc[nt][0], acc[nt][1]);
        *(float2*)&s_sims[(r + 8) * SSTR + col] = make_float2(acc[nt][2], acc[nt][3]);
    }
    __syncthreads();

    // ---- per-row epilogue (threads 0..127): top-3 + softmax (exact, stable ties)
    if (tid < ROWS) {
        const int grow = base + tid;
        float v[32];
        #pragma unroll
        for (int j = 0; j < 8; j++) {
            float4 q = *(float4*)&s_sims[tid * SSTR + 4 * j];
            v[4 * j] = q.x; v[4 * j + 1] = q.y; v[4 * j + 2] = q.z; v[4 * j + 3] = q.w;
        }
        float v0 = -2.0f, v1 = -2.0f, v2 = -2.0f;
        int   i0 = 0,     i1 = 0,     i2 = 0;
        #pragma unroll
        for (int n = 0; n < NB; n++) {
            const float x = v[n];
            if (x > v2) {
                if (x > v1) {
                    if (x > v0) { v2 = v1; i2 = i1; v1 = v0; i1 = i0; v0 = x; i0 = n; }
                    else        { v2 = v1; i2 = i1; v1 = x;  i1 = n; }
                } else          { v2 = x;  i2 = n; }
            }
        }
        if (grow < B) {
            const float e1  = __expf((v1 - v0) * 0.2f);
            const float e2  = __expf((v2 - v0) * 0.2f);
            const float inv = 1.0f / (1.0f + e1 + e2);
            s_res[tid] = make_float4(inv, e1 * inv, e2 * inv,
                                     __int_as_float(i0 | (i1 << 8) | (i2 << 16)));
            assign[grow] = (float)i0;
            atomicAdd(&s_hist[i0], 1);
        }
    }
    __syncthreads();

    // ---- coalesced act stores: one 128B STG per row (each warp its 16 rows)
    #pragma unroll 4
    for (int rr = 0; rr < 16; rr++) {
        const int rl   = w * 16 + rr;
        const int grow = base + rl;
        if (grow < B) {
            const float4 res = s_res[rl];
            const int pk = __float_as_int(res.w);
            const int i0 = pk & 255, i1 = (pk >> 8) & 255, i2 = (pk >> 16) & 255;
            float val = 0.0f;
            if (lane == i0) val = res.x;
            if (lane == i1) val = res.y;
            if (lane == i2) val = res.z;
            act[(size_t)grow * NB + lane] = val;
        }
    }

    if (tid < NB) {
        const int cnt = s_hist[tid];
        if (cnt) atomicAdd(&util[tid], (float)cnt);
    }
}

extern "C" void kernel_launch(void* const* d_in, const int* in_sizes, int n_in,
                              void* d_out, int out_size) {
    const float* z      = (const float*)d_in[0];
    const float* protos = (const float*)d_in[1];
    const float* u_in   = (const float*)d_in[2];

    const int B = in_sizes[0] / CD;

    float* out    = (float*)d_out;
    float* act    = out;
    float* assign = out + (size_t)B * NB;
    float* util   = out + (size_t)B * (NB + 1);

    cudaFuncSetAttribute(gc_main, cudaFuncAttributeMaxDynamicSharedMemorySize, SM_TOTAL);

    gc_init_util<<<1, 32>>>(u_in, util);

    const int grid = (B + ROWS - 1) / ROWS;
    gc_main<<<grid, TPB, SM_TOTAL>>>(z, protos, act, assign, util, B);
}

// round 13
// speedup vs baseline: 1.1413x; 1.1413x over previous
#include <cuda_runtime.h>
#include <cstdint>

#define NB 32
#define CD 64
#define TPB 256
#define ROWS 256

#define ZSTR 36                     // f32 stride of z chunk tile (32 dims + 4 pad)
#define BSTR 40                     // u32 stride of proto tables
#define SSTR 36                     // f32 stride of sims tile (alias of z tile)

// dynamic smem offsets (bytes)
#define SM_Z     0                  // 256 x 36 f32 = 36864 (aliased as sims later)
#define SM_BH    36864              // 64 x 40 u32 = 10240
#define SM_BM    47104              // 64 x 40 u32 = 10240
#define SM_RES   57344              // 256 x float4 = 4096
#define SM_HIST  61440              // 32 ints
#define SM_TOTAL 61568

__device__ __forceinline__ uint32_t smem_u32(const void* p) {
    uint32_t a;
    asm("{ .reg .u64 t; cvta.to.shared.u64 t, %1; cvt.u32.u64 %0, t; }" : "=r"(a) : "l"(p));
    return a;
}
__device__ __forceinline__ uint32_t f2tf(float x) {
    uint32_t r;
    asm("cvt.rna.tf32.f32 %0, %1;" : "=r"(r) : "f"(x));
    return r;
}
__device__ __forceinline__ void mma_tf32(float* c,
                                         uint32_t a0, uint32_t a1, uint32_t a2, uint32_t a3,
                                         uint32_t b0, uint32_t b1) {
    asm volatile(
        "mma.sync.aligned.m16n8k8.row.col.f32.tf32.tf32.f32 "
        "{%0,%1,%2,%3}, {%4,%5,%6,%7}, {%8,%9}, {%0,%1,%2,%3};"
        : "+f"(c[0]), "+f"(c[1]), "+f"(c[2]), "+f"(c[3])
        : "r"(a0), "r"(a1), "r"(a2), "r"(a3), "r"(b0), "r"(b1));
}
__device__ __forceinline__ void cp_async16(uint32_t saddr, const void* gaddr, uint32_t sz) {
    asm volatile("cp.async.ca.shared.global [%0], [%1], 16, %2;"
                 :: "r"(saddr), "l"(gaddr), "r"(sz) : "memory");
}

__global__ void gc_init_util(const float* __restrict__ u_in,
                             float* __restrict__ u_out) {
    int i = threadIdx.x;
    if (i < NB) u_out[i] = u_in[i];
}

__global__ __launch_bounds__(TPB, 3)
void gc_main(const float* __restrict__ z,
             const float* __restrict__ protos,
             float* __restrict__ act,
             float* __restrict__ assign,
             float* __restrict__ util,
             int B) {
    extern __shared__ char smem[];
    float*    s_z    = (float*)(smem + SM_Z);
    uint32_t* s_bh   = (uint32_t*)(smem + SM_BH);
    uint32_t* s_bm   = (uint32_t*)(smem + SM_BM);
    float*    s_sims = (float*)(smem + SM_Z);      // alias, used after sync
    float4*   s_res  = (float4*)(smem + SM_RES);
    int*      s_hist = (int*)(smem + SM_HIST);
    const uint32_t sbase = smem_u32(smem);

    const int tid  = threadIdx.x;
    const int base = blockIdx.x * ROWS;
    const int w    = tid >> 5;
    const int lane = tid & 31;
    const int g    = lane >> 2;      // groupID
    const int c    = lane & 3;       // thread-in-group

    // ---- stage protos as tf32 h/m in [k][n] layout (conflict-free LDS.32 later)
    #pragma unroll
    for (int it = 0; it < (CD * NB) / TPB; it++) {   // 8 iters
        int idx = it * TPB + tid;
        int k = idx >> 5;
        int n = idx & 31;
        float v = protos[n * CD + k];
        uint32_t h = f2tf(v);
        uint32_t m = f2tf(v - __uint_as_float(h));
        s_bh[k * BSTR + n] = h;
        s_bm[k * BSTR + n] = m;
    }
    if (tid < NB) s_hist[tid] = 0;

    float acc[2][4][4];
    #pragma unroll
    for (int t = 0; t < 2; t++)
        #pragma unroll
        for (int nt = 0; nt < 4; nt++)
            #pragma unroll
            for (int j = 0; j < 4; j++) acc[t][nt][j] = 0.0f;

    const int rb = w * 32;

    for (int ch = 0; ch < 2; ch++) {
        if (ch) __syncthreads();      // protect s_z overwrite
        // ---- stage 32-dim z chunk via cp.async (zero-fill OOB rows)
        #pragma unroll
        for (int it = 0; it < (ROWS * 8) / TPB; it++) {   // 8 iters
            int idx = it * TPB + tid;
            int row = idx >> 3;
            int d4  = idx & 7;
            int grow = base + row;
            const float* gp = z + (size_t)(grow < B ? grow : 0) * CD + ch * 32 + 4 * d4;
            uint32_t sz = (grow < B) ? 16u : 0u;
            cp_async16(sbase + SM_Z + (uint32_t)(row * ZSTR + 4 * d4) * 4, gp, sz);
        }
        asm volatile("cp.async.commit_group;");
        asm volatile("cp.async.wait_group 0;" ::: "memory");
        __syncthreads();

        // ---- 4 k-steps per chunk
        #pragma unroll
        for (int kk = 0; kk < 4; kk++) {
            const int krl = 8 * kk + c;          // local dim in chunk
            const int krg = ch * 32 + krl;       // global dim (B table index)
            // B fragments: conflict-free LDS.32
            uint32_t bh0[4], bh1[4], bm0[4], bm1[4];
            #pragma unroll
            for (int nt = 0; nt < 4; nt++) {
                const int n = nt * 8 + g;
                bh0[nt] = s_bh[krg * BSTR + n];
                bh1[nt] = s_bh[(krg + 4) * BSTR + n];
                bm0[nt] = s_bm[krg * BSTR + n];
                bm1[nt] = s_bm[(krg + 4) * BSTR + n];
            }
            // A fragments for both m16 tiles (fp32 -> tf32 h/m)
            uint32_t ah[2][4], am[2][4];
            #pragma unroll
            for (int t = 0; t < 2; t++) {
                const int r = rb + t * 16 + g;
                const float x0 = s_z[r * ZSTR + krl];
                const float x1 = s_z[(r + 8) * ZSTR + krl];
                const float x2 = s_z[r * ZSTR + krl + 4];
                const float x3 = s_z[(r + 8) * ZSTR + krl + 4];
                ah[t][0] = f2tf(x0); ah[t][1] = f2tf(x1);
                ah[t][2] = f2tf(x2); ah[t][3] = f2tf(x3);
                am[t][0] = f2tf(x0 - __uint_as_float(ah[t][0]));
                am[t][1] = f2tf(x1 - __uint_as_float(ah[t][1]));
                am[t][2] = f2tf(x2 - __uint_as_float(ah[t][2]));
                am[t][3] = f2tf(x3 - __uint_as_float(ah[t][3]));
            }
            // product-major: same-acc reuse gap = 8 (per-acc order still hh,hm,mh)
            #pragma unroll
            for (int t = 0; t < 2; t++)
                #pragma unroll
                for (int nt = 0; nt < 4; nt++)
                    mma_tf32(acc[t][nt], ah[t][0], ah[t][1], ah[t][2], ah[t][3],
                             bh0[nt], bh1[nt]);                          // hh
            #pragma unroll
            for (int t = 0; t < 2; t++)
                #pragma unroll
                for (int nt = 0; nt < 4; nt++)
                    mma_tf32(acc[t][nt], ah[t][0], ah[t][1], ah[t][2], ah[t][3],
                             bm0[nt], bm1[nt]);                          // hm
            #pragma unroll
            for (int t = 0; t < 2; t++)
                #pragma unroll
                for (int nt = 0; nt < 4; nt++)
                    mma_tf32(acc[t][nt], am[t][0], am[t][1], am[t][2], am[t][3],
                             bh0[nt], bh1[nt]);                          // mh
        }
    }
    __syncthreads();   // all z reads done; alias region as sims

    // ---- scatter C fragments to sims tile [row][32] (stride 36)
    #pragma unroll
    for (int t = 0; t < 2; t++) {
        const int r = rb + t * 16 + g;
        #pragma unroll
        for (int nt = 0; nt < 4; nt++) {
            const int col = nt * 8 + 2 * c;
            *(float2*)&s_sims[r * SSTR + col]       = make_float2(acc[t][nt][0], acc[t][nt][1]);
            *(float2*)&s_sims[(r + 8) * SSTR + col] = make_float2(acc[t][nt][2], acc[t][nt][3]);
        }
    }
    __syncthreads();

    // ---- per-thread row epilogue: top-3 + softmax (exact, stable ties)
    {
        const int grow = base + tid;
        float v[32];
        #pragma unroll
        for (int j = 0; j < 8; j++) {
            float4 q = *(float4*)&s_sims[tid * SSTR + 4 * j];
            v[4 * j] = q.x; v[4 * j + 1] = q.y; v[4 * j + 2] = q.z; v[4 * j + 3] = q.w;
        }
        float v0 = -2.0f, v1 = -2.0f, v2 = -2.0f;
        int   i0 = 0,     i1 = 0,     i2 = 0;
        #pragma unroll
        for (int n = 0; n < NB; n++) {
            const float x = v[n];
            if (x > v2) {
                if (x > v1) {
                    if (x > v0) { v2 = v1; i2 = i1; v1 = v0; i1 = i0; v0 = x; i0 = n; }
                    else        { v2 = v1; i2 = i1; v1 = x;  i1 = n; }
                } else          { v2 = x;  i2 = n; }
            }
        }
        if (grow < B) {
            const float e1  = __expf((v1 - v0) * 0.2f);
            const float e2  = __expf((v2 - v0) * 0.2f);
            const float inv = 1.0f / (1.0f + e1 + e2);
            s_res[tid] = make_float4(inv, e1 * inv, e2 * inv,
                                     __int_as_float(i0 | (i1 << 8) | (i2 << 16)));
            assign[grow] = (float)i0;
            atomicAdd(&s_hist[i0], 1);
        }
    }
    __syncthreads();

    // ---- coalesced act stores: one 128B STG per row (each warp its 32 rows)
    #pragma unroll 4
    for (int r = 0; r < 32; r++) {
        const int rl   = w * 32 + r;
        const int grow = base + rl;
        if (grow < B) {
            const float4 res = s_res[rl];
            const int pk = __float_as_int(res.w);
            const int i0 = pk & 255, i1 = (pk >> 8) & 255, i2 = (pk >> 16) & 255;
            float val = 0.0f;
            if (lane == i0) val = res.x;
            if (lane == i1) val = res.y;
            if (lane == i2) val = res.z;
            act[(size_t)grow * NB + lane] = val;
        }
    }

    if (tid < NB) {
        const int cnt = s_hist[tid];
        if (cnt) atomicAdd(&util[tid], (float)cnt);
    }
}

extern "C" void kernel_launch(void* const* d_in, const int* in_sizes, int n_in,
                              void* d_out, int out_size) {
    const float* z      = (const float*)d_in[0];
    const float* protos = (const float*)d_in[1];
    const float* u_in   = (const float*)d_in[2];

    const int B = in_sizes[0] / CD;

    float* out    = (float*)d_out;
    float* act    = out;
    float* assign = out + (size_t)B * NB;
    float* util   = out + (size_t)B * (NB + 1);

    cudaFuncSetAttribute(gc_main, cudaFuncAttributeMaxDynamicSharedMemorySize, SM_TOTAL);

    gc_init_util<<<1, 32>>>(u_in, util);

    const int grid = (B + ROWS - 1) / ROWS;
    gc_main<<<grid, TPB, SM_TOTAL>>>(z, protos, act, assign, util, B);
}